// round 1
// baseline (speedup 1.0000x reference)
#include <cuda_runtime.h>
#include <math.h>

#define BATCH 16
#define DIM 48
#define HID 16
#define CH 8
#define IMH 256
#define IMW 256
#define HXW (IMH*IMW)
#define TW 32
#define TH 16
#define HLW (TW+2)   // 34
#define HLH (TH+2)   // 18
#define NTHREADS 256

__device__ __forceinline__ float gelu_exact(float v) {
    return 0.5f * v * (1.0f + erff(v * 0.70710678118654752f));
}

__global__ __launch_bounds__(NTHREADS, 2)
void fused_block_kernel(const float* __restrict__ x,
                        const float* __restrict__ W1,
                        const float* __restrict__ b1,
                        const float* __restrict__ gamma,
                        const float* __restrict__ beta,
                        const float* __restrict__ dww,
                        const float* __restrict__ dwb,
                        const float* __restrict__ pww,
                        const float* __restrict__ pwb,
                        const float* __restrict__ W2,
                        const float* __restrict__ b2,
                        float* __restrict__ out)
{
    __shared__ float sW1[DIM * HID];          // [d][h]
    __shared__ float sW2[CH * DIM];           // [c][d]
    __shared__ float sb1[HID];
    __shared__ float sb2[DIM];
    __shared__ float sg[CH], sbt[CH];
    __shared__ float sdw[CH * 9], sdwb[CH];
    __shared__ float spw[CH * CH], spwb[CH];
    __shared__ float sn[CH][HLH][HLW];        // layernormed x2, halo tile, per-channel planes
    __shared__ float sx1[CH][HLH][HLW];       // gate input x1 (valid in interior)

    const int tid = threadIdx.x;

    // ---- load weights to shared ----
    for (int i = tid; i < DIM * HID; i += NTHREADS) sW1[i] = W1[i];
    for (int i = tid; i < CH * DIM;  i += NTHREADS) sW2[i] = W2[i];
    if (tid < HID) sb1[tid] = b1[tid];
    if (tid < DIM) sb2[tid] = b2[tid];
    if (tid < CH) {
        sg[tid]  = gamma[tid];
        sbt[tid] = beta[tid];
        sdwb[tid] = dwb[tid];
        spwb[tid] = pwb[tid];
    }
    for (int i = tid; i < CH * 9;  i += NTHREADS) sdw[i] = dww[i];
    for (int i = tid; i < CH * CH; i += NTHREADS) spw[i] = pww[i];

    const int x0 = blockIdx.x * TW;
    const int y0 = blockIdx.y * TH;
    const int bb = blockIdx.z;
    const float* __restrict__ xin = x + (size_t)bb * (DIM * HXW);

    __syncthreads();

    // ---- Phase 1: GEMM1 + gelu^2 + LN for halo tile ----
    for (int hp = tid; hp < HLH * HLW; hp += NTHREADS) {
        const int hy = hp / HLW;
        const int hx = hp - hy * HLW;
        const int gy = y0 + hy - 1;
        const int gx = x0 + hx - 1;

        if ((unsigned)gy >= IMH || (unsigned)gx >= IMW) {
            // conv 'SAME' zero padding
            #pragma unroll
            for (int c = 0; c < CH; c++) sn[c][hy][hx] = 0.0f;
            continue;
        }

        const int p = gy * IMW + gx;
        const float4* __restrict__ tv4 = (const float4*)(xin + (size_t)p * DIM);

        float acc[HID];
        #pragma unroll
        for (int h = 0; h < HID; h++) acc[h] = sb1[h];

        #pragma unroll
        for (int dq = 0; dq < DIM / 4; dq++) {
            const float4 tv = tv4[dq];
            const float tvs[4] = {tv.x, tv.y, tv.z, tv.w};
            #pragma unroll
            for (int j = 0; j < 4; j++) {
                const float td = tvs[j];
                const float* wr = &sW1[(dq * 4 + j) * HID];
                #pragma unroll
                for (int h = 0; h < HID; h++) acc[h] += td * wr[h];
            }
        }

        // gelu(gelu(.)) exact
        #pragma unroll
        for (int h = 0; h < HID; h++) {
            float v = gelu_exact(acc[h]);
            acc[h] = gelu_exact(v);
        }

        // layernorm over channels 8..15
        float m = 0.0f;
        #pragma unroll
        for (int c = 0; c < CH; c++) m += acc[CH + c];
        m *= (1.0f / CH);
        float var = 0.0f;
        #pragma unroll
        for (int c = 0; c < CH; c++) { float d = acc[CH + c] - m; var += d * d; }
        var *= (1.0f / CH);
        const float inv = rsqrtf(var + 1e-5f);

        #pragma unroll
        for (int c = 0; c < CH; c++)
            sn[c][hy][hx] = (acc[CH + c] - m) * inv * sg[c] + sbt[c];
        #pragma unroll
        for (int c = 0; c < CH; c++)
            sx1[c][hy][hx] = acc[c];
    }

    __syncthreads();

    // ---- Phase 2: dw conv + pw conv + gate + GEMM2 + store ----
    float* __restrict__ outb = out + (size_t)bb * (DIM * HXW);

    #pragma unroll
    for (int it = 0; it < (TH * TW) / NTHREADS; it++) {
        const int p  = tid + it * NTHREADS;
        const int ly = p / TW;
        const int lx = p - ly * TW;
        const int hy = ly + 1;
        const int hx = lx + 1;

        float ncen[CH];
        #pragma unroll
        for (int c = 0; c < CH; c++) ncen[c] = sn[c][hy][hx];

        float g[CH];
        #pragma unroll
        for (int c = 0; c < CH; c++) {
            float sp = sdwb[c];
            #pragma unroll
            for (int ky = 0; ky < 3; ky++) {
                #pragma unroll
                for (int kx = 0; kx < 3; kx++) {
                    sp += sn[c][hy + ky - 1][hx + kx - 1] * sdw[c * 9 + ky * 3 + kx];
                }
            }
            float chv = spwb[c];
            #pragma unroll
            for (int ci = 0; ci < CH; ci++) chv += spw[c * CH + ci] * ncen[ci];
            g[c] = sx1[c][hy][hx] * sp * chv;
        }

        float oacc[DIM];
        #pragma unroll
        for (int d = 0; d < DIM; d++) oacc[d] = sb2[d];
        #pragma unroll
        for (int c = 0; c < CH; c++) {
            const float gc = g[c];
            const float* wr = &sW2[c * DIM];
            #pragma unroll
            for (int d = 0; d < DIM; d++) oacc[d] += gc * wr[d];
        }

        const int gp = (y0 + ly) * IMW + (x0 + lx);
        #pragma unroll
        for (int d = 0; d < DIM; d++)
            outb[(size_t)d * HXW + gp] = oacc[d];
    }
}

extern "C" void kernel_launch(void* const* d_in, const int* in_sizes, int n_in,
                              void* d_out, int out_size)
{
    const float* x     = (const float*)d_in[0];
    const float* W1    = (const float*)d_in[1];
    const float* b1    = (const float*)d_in[2];
    const float* gamma = (const float*)d_in[3];
    const float* beta  = (const float*)d_in[4];
    const float* dww   = (const float*)d_in[5];
    const float* dwb   = (const float*)d_in[6];
    const float* pww   = (const float*)d_in[7];
    const float* pwb   = (const float*)d_in[8];
    const float* W2    = (const float*)d_in[9];
    const float* b2    = (const float*)d_in[10];
    float* out = (float*)d_out;

    dim3 grid(IMW / TW, IMH / TH, BATCH);   // 8 x 16 x 16
    fused_block_kernel<<<grid, NTHREADS>>>(x, W1, b1, gamma, beta,
                                           dww, dwb, pww, pwb, W2, b2, out);
}